// round 1
// baseline (speedup 1.0000x reference)
#include <cuda_runtime.h>
#include <cuda_bf16.h>

// Problem shape (fixed)
#define BB 16
#define CC 512
#define LL 4096
// qkv rows = 3*CC = 1536

// Scratch (device globals: no allocation allowed)
__device__ float g_qkv[(size_t)BB * 3 * CC * LL];   // [16][1536][4096]  ~403 MB
__device__ float g_ctx[(size_t)BB * CC * CC];       // [16][512][512]
__device__ float g_M[(size_t)BB * CC * CC];         // [16][512][512]

// ---------------------------------------------------------------------------
// Tiled SGEMM: C[m,n] = sum_k A[m,k] * B'[k,n]  (+ bias[m])
//   TRANS_B=false: B is [K,N] row-major
//   TRANS_B=true : B is [N,K] row-major (so B'[k,n] = B[n,k])
// Block tile 128x128, K-step 8, 256 threads, 8x8 per thread.
// All dims must be multiples of tile sizes (true for this problem).
// blockIdx.z = batch; strides in elements (stride 0 = shared operand).
// ---------------------------------------------------------------------------
template <bool TRANS_B, bool ADD_BIAS>
__global__ __launch_bounds__(256) void sgemm_k(
    const float* __restrict__ A, const float* __restrict__ Bm,
    float* __restrict__ Cm, const float* __restrict__ bias,
    int M, int N, int K, long sA, long sB, long sC)
{
    A  += (long)blockIdx.z * sA;
    Bm += (long)blockIdx.z * sB;
    Cm += (long)blockIdx.z * sC;

    __shared__ float As[8][128];
    __shared__ float Bs[8][128];

    const int tid = threadIdx.x;
    const int m0 = blockIdx.y * 128;
    const int n0 = blockIdx.x * 128;

    const int tr = (tid / 16) * 8;   // row offset of this thread's 8x8 micro-tile
    const int tc = (tid % 16) * 8;   // col offset

    // A tile load mapping: 128 rows x 8 cols, one float4 per thread
    const int arow = tid >> 1;
    const int acol = (tid & 1) * 4;
    // B tile load mapping
    const int brow = TRANS_B ? (tid >> 1) : (tid >> 5);        // NT: 128 n-rows; NN: 8 k-rows
    const int bcol = TRANS_B ? ((tid & 1) * 4) : ((tid & 31) * 4);

    float acc[8][8] = {};

    for (int k0 = 0; k0 < K; k0 += 8) {
        // --- load A tile (transpose into As[k][m]) ---
        {
            float4 av = *reinterpret_cast<const float4*>(&A[(long)(m0 + arow) * K + (k0 + acol)]);
            As[acol + 0][arow] = av.x;
            As[acol + 1][arow] = av.y;
            As[acol + 2][arow] = av.z;
            As[acol + 3][arow] = av.w;
        }
        // --- load B tile into Bs[k][n] ---
        if (TRANS_B) {
            float4 bv = *reinterpret_cast<const float4*>(&Bm[(long)(n0 + brow) * K + (k0 + bcol)]);
            Bs[bcol + 0][brow] = bv.x;
            Bs[bcol + 1][brow] = bv.y;
            Bs[bcol + 2][brow] = bv.z;
            Bs[bcol + 3][brow] = bv.w;
        } else {
            float4 bv = *reinterpret_cast<const float4*>(&Bm[(long)(k0 + brow) * N + (n0 + bcol)]);
            *reinterpret_cast<float4*>(&Bs[brow][bcol]) = bv;
        }
        __syncthreads();

        #pragma unroll
        for (int kk = 0; kk < 8; kk++) {
            float a[8], b[8];
            #pragma unroll
            for (int i = 0; i < 8; i++) a[i] = As[kk][tr + i];
            #pragma unroll
            for (int j = 0; j < 8; j++) b[j] = Bs[kk][tc + j];
            #pragma unroll
            for (int i = 0; i < 8; i++)
                #pragma unroll
                for (int j = 0; j < 8; j++)
                    acc[i][j] += a[i] * b[j];
        }
        __syncthreads();
    }

    // --- epilogue ---
    #pragma unroll
    for (int i = 0; i < 8; i++) {
        const int r = m0 + tr + i;
        const float bv = ADD_BIAS ? bias[r] : 0.0f;
        #pragma unroll
        for (int j = 0; j < 8; j += 4) {
            float4 o;
            o.x = acc[i][j + 0] + bv;
            o.y = acc[i][j + 1] + bv;
            o.z = acc[i][j + 2] + bv;
            o.w = acc[i][j + 3] + bv;
            *reinterpret_cast<float4*>(&Cm[(long)r * N + (n0 + tc + j)]) = o;
        }
    }
}

// ---------------------------------------------------------------------------
// In-place softmax over the last dim (L=4096) of the k-slice of g_qkv.
// grid = (512, 16); block = 256 threads; each thread handles 16 elements.
// ---------------------------------------------------------------------------
__global__ __launch_bounds__(256) void softmax_k(float* __restrict__ qkv)
{
    const int r = blockIdx.x;          // channel within k: 0..511
    const int b = blockIdx.y;          // batch
    float* p = qkv + ((long)b * (3 * CC) + CC + r) * LL;

    const int tid = threadIdx.x;
    __shared__ float red[8];

    float v[16];
    float mx = -1e30f;
    #pragma unroll
    for (int i = 0; i < 16; i++) {
        v[i] = p[tid + i * 256];
        mx = fmaxf(mx, v[i]);
    }
    // block max
    #pragma unroll
    for (int o = 16; o > 0; o >>= 1) mx = fmaxf(mx, __shfl_xor_sync(0xffffffffu, mx, o));
    if ((tid & 31) == 0) red[tid >> 5] = mx;
    __syncthreads();
    if (tid < 32) {
        float m2 = (tid < 8) ? red[tid] : -1e30f;
        #pragma unroll
        for (int o = 4; o > 0; o >>= 1) m2 = fmaxf(m2, __shfl_xor_sync(0xffffffffu, m2, o));
        if (tid == 0) red[0] = m2;
    }
    __syncthreads();
    mx = red[0];
    __syncthreads();

    float s = 0.0f;
    #pragma unroll
    for (int i = 0; i < 16; i++) {
        v[i] = __expf(v[i] - mx);
        s += v[i];
    }
    #pragma unroll
    for (int o = 16; o > 0; o >>= 1) s += __shfl_xor_sync(0xffffffffu, s, o);
    if ((tid & 31) == 0) red[tid >> 5] = s;
    __syncthreads();
    if (tid < 32) {
        float s2 = (tid < 8) ? red[tid] : 0.0f;
        #pragma unroll
        for (int o = 4; o > 0; o >>= 1) s2 += __shfl_xor_sync(0xffffffffu, s2, o);
        if (tid == 0) red[0] = s2;
    }
    __syncthreads();
    const float inv = 1.0f / red[0];

    #pragma unroll
    for (int i = 0; i < 16; i++) p[tid + i * 256] = v[i] * inv;
}

// ---------------------------------------------------------------------------
extern "C" void kernel_launch(void* const* d_in, const int* in_sizes, int n_in,
                              void* d_out, int out_size)
{
    // Match inputs by element count (all distinct):
    //   x: 16*512*4096 = 33554432, w_qkv: 1536*512 = 786432,
    //   w_out: 512*512 = 262144, b_out: 512
    const float* x = nullptr; const float* w_qkv = nullptr;
    const float* w_out = nullptr; const float* b_out = nullptr;
    for (int i = 0; i < n_in; i++) {
        switch (in_sizes[i]) {
            case 33554432: x     = (const float*)d_in[i]; break;
            case 786432:   w_qkv = (const float*)d_in[i]; break;
            case 262144:   w_out = (const float*)d_in[i]; break;
            case 512:      b_out = (const float*)d_in[i]; break;
            default: break;
        }
    }
    float* y = (float*)d_out;

    float *qkv, *ctx, *Mm;
    cudaGetSymbolAddress((void**)&qkv, g_qkv);
    cudaGetSymbolAddress((void**)&ctx, g_ctx);
    cudaGetSymbolAddress((void**)&Mm,  g_M);

    const long sQKV = (long)3 * CC * LL;   // per-batch qkv stride
    const long sX   = (long)CC * LL;       // per-batch x / y stride
    const long sCtx = (long)CC * CC;

    // 1) qkv[b] = w_qkv @ x[b]          [1536,512] @ [512,4096]
    sgemm_k<false, false><<<dim3(LL / 128, (3 * CC) / 128, BB), 256>>>(
        w_qkv, x, qkv, nullptr, 3 * CC, LL, CC, 0, sX, sQKV);

    // 2) softmax over L on the k slice (rows 512..1023 of each batch)
    softmax_k<<<dim3(CC, BB), 256>>>(qkv);

    // 3) ctx[b] = k_sm[b] @ v[b]^T      [512,4096] @ [4096,512] (NT)
    sgemm_k<true, false><<<dim3(CC / 128, CC / 128, BB), 256>>>(
        qkv + (long)CC * LL,            // k slice
        qkv + (long)2 * CC * LL,        // v slice
        ctx, nullptr, CC, CC, LL, sQKV, sQKV, sCtx);

    // 4) M[b] = w_out @ ctx[b]^T       [512,512] @ [512,512] (NT)
    sgemm_k<true, false><<<dim3(CC / 128, CC / 128, BB), 256>>>(
        w_out, ctx, Mm, nullptr, CC, CC, CC, 0, sCtx, sCtx);

    // 5) y[b] = M[b] @ q[b] + b_out    [512,512] @ [512,4096] (NN, bias)
    sgemm_k<false, true><<<dim3(LL / 128, CC / 128, BB), 256>>>(
        Mm, qkv /* q slice = offset 0 */, y, b_out, CC, LL, CC, sCtx, sQKV, sX);

    (void)out_size;
}

// round 3
// speedup vs baseline: 2.1745x; 2.1745x over previous
#include <cuda_runtime.h>
#include <cuda_bf16.h>
#include <cstdint>

// Problem shape (fixed)
#define BB 16
#define CC 512
#define LL 4096

// Scratch (device globals: no allocation allowed)
__device__ float g_qkv[(size_t)BB * 3 * CC * LL];   // [16][1536][4096]
__device__ float g_ctx[(size_t)BB * CC * CC];       // [16][512][512]
__device__ float g_M[(size_t)BB * CC * CC];         // [16][512][512]

__device__ __forceinline__ uint32_t smem_u32(const void* p) {
    uint32_t a;
    asm("{ .reg .u64 t; cvta.to.shared.u64 t, %1; cvt.u32.u64 %0, t; }" : "=r"(a) : "l"(p));
    return a;
}

#define LDSM4(r0, r1, r2, r3, addr) \
    asm volatile("ldmatrix.sync.aligned.m8n8.x4.shared.b16 {%0,%1,%2,%3}, [%4];" \
                 : "=r"(r0), "=r"(r1), "=r"(r2), "=r"(r3) : "r"(addr))
#define LDSM4T(r0, r1, r2, r3, addr) \
    asm volatile("ldmatrix.sync.aligned.m8n8.x4.trans.shared.b16 {%0,%1,%2,%3}, [%4];" \
                 : "=r"(r0), "=r"(r1), "=r"(r2), "=r"(r3) : "r"(addr))

#define MMA16816(c, a, b) \
    asm volatile("mma.sync.aligned.m16n8k16.row.col.f32.bf16.bf16.f32 " \
                 "{%0,%1,%2,%3}, {%4,%5,%6,%7}, {%8,%9}, {%0,%1,%2,%3};" \
                 : "+f"((c)[0]), "+f"((c)[1]), "+f"((c)[2]), "+f"((c)[3]) \
                 : "r"((a)[0]), "r"((a)[1]), "r"((a)[2]), "r"((a)[3]), \
                   "r"((b)[0]), "r"((b)[1]))

// split one fp32 into bf16 hi + bf16 lo (residual)
__device__ __forceinline__ void split2(float f0, float f1, uint32_t& hi, uint32_t& lo) {
    __nv_bfloat162 h = __floats2bfloat162_rn(f0, f1);
    float r0 = f0 - __bfloat162float(h.x);
    float r1 = f1 - __bfloat162float(h.y);
    __nv_bfloat162 l = __floats2bfloat162_rn(r0, r1);
    hi = *reinterpret_cast<uint32_t*>(&h);
    lo = *reinterpret_cast<uint32_t*>(&l);
}

// ============================================================================
// wgemm: C[m,n] (+bias[m]) = sum_k A[m,k] * B'[k,n], fp32 in/out, bf16x3 HMMA.
//   B_IS_KN=true : B stored [K,N] row-major (NN)
//   B_IS_KN=false: B stored [N,K] row-major (NT)
// Block tile 128x128, K-chunk 32, 256 threads (8 warps 2x4), warp tile 64x32.
// Dims must be multiples of 128/128/32 (true here). blockIdx.z = batch.
// ============================================================================
#define WG_SMEM 65536      // 2 buffers x 32KB
// per-buffer plane offsets
#define P_AH 0
#define P_AL 8192
#define P_BH 16384
#define P_BL 24576

template <bool B_IS_KN, bool ADD_BIAS>
__global__ __launch_bounds__(256, 1) void wgemm(
    const float* __restrict__ A, const float* __restrict__ B,
    float* __restrict__ C, const float* __restrict__ bias,
    int N, int K, long sA, long sB, long sC,
    int lda, int ldb, int ldc)
{
    extern __shared__ char smem[];
    const uint32_t sb = smem_u32(smem);

    const int tid  = threadIdx.x;
    const int lane = tid & 31;
    const int wid  = tid >> 5;
    const int wm   = wid >> 2;          // 0..1
    const int wn   = wid & 3;           // 0..3
    const int m0 = blockIdx.y * 128;
    const int n0 = blockIdx.x * 128;
    const long z = blockIdx.z;

    A += z * sA + (long)m0 * lda;
    B += z * sB + (B_IS_KN ? (long)n0 : (long)n0 * ldb);
    C += z * sC;

    const int ln15 = lane & 15;
    const int grp  = lane >> 4;         // 0/1
    const int sw64 = (ln15 >> 1) & 3;   // swizzle for 64B-row planes

    float acc[4][4][4];
    #pragma unroll
    for (int i = 0; i < 4; i++)
        #pragma unroll
        for (int j = 0; j < 4; j++)
            #pragma unroll
            for (int q = 0; q < 4; q++) acc[i][j][q] = 0.0f;

    // ---------------- loaders ----------------
    float ra[16], rb[16];

    auto load_regs = [&](int c) {
        const int k0 = c * 32;
        {
            const float* pa = A + (long)(tid >> 1) * lda + k0 + (tid & 1) * 16;
            #pragma unroll
            for (int t = 0; t < 4; t++) {
                float4 v = *reinterpret_cast<const float4*>(pa + t * 4);
                ra[t * 4 + 0] = v.x; ra[t * 4 + 1] = v.y;
                ra[t * 4 + 2] = v.z; ra[t * 4 + 3] = v.w;
            }
        }
        if (B_IS_KN) {
            const float* pb = B + (long)(k0 + (tid >> 3)) * ldb + (tid & 7) * 16;
            #pragma unroll
            for (int t = 0; t < 4; t++) {
                float4 v = *reinterpret_cast<const float4*>(pb + t * 4);
                rb[t * 4 + 0] = v.x; rb[t * 4 + 1] = v.y;
                rb[t * 4 + 2] = v.z; rb[t * 4 + 3] = v.w;
            }
        } else {
            const float* pb = B + (long)(tid >> 1) * ldb + k0 + (tid & 1) * 16;
            #pragma unroll
            for (int t = 0; t < 4; t++) {
                float4 v = *reinterpret_cast<const float4*>(pb + t * 4);
                rb[t * 4 + 0] = v.x; rb[t * 4 + 1] = v.y;
                rb[t * 4 + 2] = v.z; rb[t * 4 + 3] = v.w;
            }
        }
    };

    // write 16 values as hi/lo into a 64B-row plane at (row, kq..kq+15)
    auto store_row64 = [&](char* ph, char* pl, int row, int kq, const float* f) {
        uint32_t hi[8], lo[8];
        #pragma unroll
        for (int t = 0; t < 8; t++) split2(f[2 * t], f[2 * t + 1], hi[t], lo[t]);
        const int sw = (row >> 1) & 3;
        const int c0 = kq >> 3;
        char* h0 = ph + row * 64 + (((c0    ) ^ sw) & 3) * 16;
        char* h1 = ph + row * 64 + (((c0 + 1) ^ sw) & 3) * 16;
        char* l0 = pl + row * 64 + (((c0    ) ^ sw) & 3) * 16;
        char* l1 = pl + row * 64 + (((c0 + 1) ^ sw) & 3) * 16;
        *reinterpret_cast<uint4*>(h0) = make_uint4(hi[0], hi[1], hi[2], hi[3]);
        *reinterpret_cast<uint4*>(h1) = make_uint4(hi[4], hi[5], hi[6], hi[7]);
        *reinterpret_cast<uint4*>(l0) = make_uint4(lo[0], lo[1], lo[2], lo[3]);
        *reinterpret_cast<uint4*>(l1) = make_uint4(lo[4], lo[5], lo[6], lo[7]);
    };

    auto store_smem = [&](int b) {
        char* base = smem + b * 32768;
        store_row64(base + P_AH, base + P_AL, tid >> 1, (tid & 1) * 16, ra);
        if (!B_IS_KN) {
            store_row64(base + P_BH, base + P_BL, tid >> 1, (tid & 1) * 16, rb);
        } else {
            // B tile 32k x 128n stored as [k][n]: row k = 256B, chunk swizzle c^(k&7)
            char* bh = base + P_BH;
            char* bl = base + P_BL;
            const int k  = tid >> 3;
            const int nq = (tid & 7) * 16;
            #pragma unroll
            for (int t = 0; t < 4; t++) {
                uint32_t h0, h1, l0, l1;
                split2(rb[4 * t + 0], rb[4 * t + 1], h0, l0);
                split2(rb[4 * t + 2], rb[4 * t + 3], h1, l1);
                const int nn  = nq + 4 * t;
                const int c   = nn >> 3;
                const int off = (nn & 7) * 2;
                char* dh = bh + k * 256 + ((c ^ (k & 7)) & 15) * 16 + off;
                char* dl = bl + k * 256 + ((c ^ (k & 7)) & 15) * 16 + off;
                *reinterpret_cast<uint2*>(dh) = make_uint2(h0, h1);
                *reinterpret_cast<uint2*>(dl) = make_uint2(l0, l1);
            }
        }
    };

    // ---------------- fragment loads ----------------
    // A: [m][k] 64B rows. precompute per-i row offsets
    int a_row_off[4];
    #pragma unroll
    for (int i = 0; i < 4; i++)
        a_row_off[i] = (wm * 64 + i * 16 + ln15) * 64;
    // B NT: [n][k] 64B rows
    int b_row_off[2];
    #pragma unroll
    for (int jp = 0; jp < 2; jp++)
        b_row_off[jp] = (wn * 32 + jp * 16 + ln15) * 64;
    // B KN: [k][n] 256B rows
    const int kn_k7 = ln15 & 7;

    auto lda_frags = [&](uint32_t plane, int ks, uint32_t af[4][4]) {
        const int c = ks * 2 + grp;
        #pragma unroll
        for (int i = 0; i < 4; i++) {
            uint32_t addr = plane + a_row_off[i] + (((c ^ sw64) & 3) << 4);
            LDSM4(af[i][0], af[i][1], af[i][2], af[i][3], addr);
        }
    };
    auto ldb_frags = [&](uint32_t plane, int ks, uint32_t bf[4][2]) {
        if (B_IS_KN) {
            const uint32_t krow = (uint32_t)(ks * 16 + ln15) << 8;
            #pragma unroll
            for (int jp = 0; jp < 2; jp++) {
                const int cn = wn * 4 + jp * 2 + grp;
                uint32_t addr = plane + krow + (((cn ^ kn_k7) & 15) << 4);
                uint32_t r0, r1, r2, r3;
                LDSM4T(r0, r1, r2, r3, addr);
                bf[jp * 2    ][0] = r0; bf[jp * 2    ][1] = r1;
                bf[jp * 2 + 1][0] = r2; bf[jp * 2 + 1][1] = r3;
            }
        } else {
            const int c = ks * 2 + grp;
            #pragma unroll
            for (int jp = 0; jp < 2; jp++) {
                uint32_t addr = plane + b_row_off[jp] + (((c ^ sw64) & 3) << 4);
                uint32_t r0, r1, r2, r3;
                LDSM4(r0, r1, r2, r3, addr);
                bf[jp * 2    ][0] = r0; bf[jp * 2    ][1] = r2;
                bf[jp * 2 + 1][0] = r1; bf[jp * 2 + 1][1] = r3;
            }
        }
    };

    auto mma_pass = [&](uint32_t af[4][4], uint32_t bf[4][2]) {
        #pragma unroll
        for (int i = 0; i < 4; i++)
            #pragma unroll
            for (int j = 0; j < 4; j++)
                MMA16816(acc[i][j], af[i], bf[j]);
    };

    auto compute_chunk = [&](int b) {
        const uint32_t base = sb + b * 32768;
        #pragma unroll
        for (int ks = 0; ks < 2; ks++) {
            uint32_t ah[4][4], bh[4][2];
            lda_frags(base + P_AH, ks, ah);
            ldb_frags(base + P_BH, ks, bh);
            mma_pass(ah, bh);                 // Ahi * Bhi
            {
                uint32_t bl[4][2];
                ldb_frags(base + P_BL, ks, bl);
                mma_pass(ah, bl);             // Ahi * Blo
            }
            {
                uint32_t al[4][4];
                lda_frags(base + P_AL, ks, al);
                mma_pass(al, bh);             // Alo * Bhi
            }
        }
    };

    // ---------------- main loop ----------------
    const int NC = K >> 5;

    load_regs(0);
    store_smem(0);
    __syncthreads();

    for (int c = 0; c < NC; c++) {
        if (c + 1 < NC) load_regs(c + 1);
        compute_chunk(c & 1);
        __syncthreads();
        if (c + 1 < NC) {
            store_smem((c + 1) & 1);
            __syncthreads();
        }
    }

    // ---------------- epilogue ----------------
    #pragma unroll
    for (int i = 0; i < 4; i++) {
        const int row = m0 + wm * 64 + i * 16 + (lane >> 2);
        float bv0 = 0.0f, bv1 = 0.0f;
        if (ADD_BIAS) { bv0 = bias[row]; bv1 = bias[row + 8]; }
        #pragma unroll
        for (int j = 0; j < 4; j++) {
            const int col = n0 + wn * 32 + j * 8 + (lane & 3) * 2;
            float2 v0 = make_float2(acc[i][j][0] + bv0, acc[i][j][1] + bv0);
            float2 v1 = make_float2(acc[i][j][2] + bv1, acc[i][j][3] + bv1);
            *reinterpret_cast<float2*>(&C[(long)row * ldc + col])       = v0;
            *reinterpret_cast<float2*>(&C[(long)(row + 8) * ldc + col]) = v1;
        }
    }
}

// ============================================================================
// Softmax over L on the k-slice of qkv
// ============================================================================
__global__ __launch_bounds__(256) void softmax_k(float* __restrict__ qkv)
{
    const int r = blockIdx.x;
    const int b = blockIdx.y;
    float* p = qkv + ((long)b * (3 * CC) + CC + r) * LL;
    const int tid = threadIdx.x;
    __shared__ float red[8];

    float v[16];
    float mx = -1e30f;
    #pragma unroll
    for (int i = 0; i < 16; i++) { v[i] = p[tid + i * 256]; mx = fmaxf(mx, v[i]); }
    #pragma unroll
    for (int o = 16; o > 0; o >>= 1) mx = fmaxf(mx, __shfl_xor_sync(0xffffffffu, mx, o));
    if ((tid & 31) == 0) red[tid >> 5] = mx;
    __syncthreads();
    if (tid < 32) {
        float m2 = (tid < 8) ? red[tid] : -1e30f;
        #pragma unroll
        for (int o = 4; o > 0; o >>= 1) m2 = fmaxf(m2, __shfl_xor_sync(0xffffffffu, m2, o));
        if (tid == 0) red[0] = m2;
    }
    __syncthreads();
    mx = red[0];
    __syncthreads();

    float s = 0.0f;
    #pragma unroll
    for (int i = 0; i < 16; i++) { v[i] = __expf(v[i] - mx); s += v[i]; }
    #pragma unroll
    for (int o = 16; o > 0; o >>= 1) s += __shfl_xor_sync(0xffffffffu, s, o);
    if ((tid & 31) == 0) red[tid >> 5] = s;
    __syncthreads();
    if (tid < 32) {
        float s2 = (tid < 8) ? red[tid] : 0.0f;
        #pragma unroll
        for (int o = 4; o > 0; o >>= 1) s2 += __shfl_xor_sync(0xffffffffu, s2, o);
        if (tid == 0) red[0] = s2;
    }
    __syncthreads();
    const float inv = 1.0f / red[0];
    #pragma unroll
    for (int i = 0; i < 16; i++) p[tid + i * 256] = v[i] * inv;
}

// ============================================================================
extern "C" void kernel_launch(void* const* d_in, const int* in_sizes, int n_in,
                              void* d_out, int out_size)
{
    const float* x = nullptr; const float* w_qkv = nullptr;
    const float* w_out = nullptr; const float* b_out = nullptr;
    for (int i = 0; i < n_in; i++) {
        switch (in_sizes[i]) {
            case 33554432: x     = (const float*)d_in[i]; break;
            case 786432:   w_qkv = (const float*)d_in[i]; break;
            case 262144:   w_out = (const float*)d_in[i]; break;
            case 512:      b_out = (const float*)d_in[i]; break;
            default: break;
        }
    }
    float* y = (float*)d_out;

    float *qkv, *ctx, *Mm;
    cudaGetSymbolAddress((void**)&qkv, g_qkv);
    cudaGetSymbolAddress((void**)&ctx, g_ctx);
    cudaGetSymbolAddress((void**)&Mm,  g_M);

    cudaFuncSetAttribute(wgemm<true,  false>, cudaFuncAttributeMaxDynamicSharedMemorySize, WG_SMEM);
    cudaFuncSetAttribute(wgemm<false, false>, cudaFuncAttributeMaxDynamicSharedMemorySize, WG_SMEM);
    cudaFuncSetAttribute(wgemm<true,  true >, cudaFuncAttributeMaxDynamicSharedMemorySize, WG_SMEM);

    const long sQKV = (long)3 * CC * LL;
    const long sX   = (long)CC * LL;
    const long sCtx = (long)CC * CC;

    // 1) qkv[b] = w_qkv @ x[b]        (NN: B = x stored [K=512, N=4096])
    wgemm<true, false><<<dim3(LL / 128, (3 * CC) / 128, BB), 256, WG_SMEM>>>(
        w_qkv, x, qkv, nullptr, LL, CC, 0, sX, sQKV, CC, LL, LL);

    // 2) softmax over L on k slice
    softmax_k<<<dim3(CC, BB), 256>>>(qkv);

    // 3) ctx[b] = k_sm[b] @ v[b]^T    (NT: B = v stored [N=512, K=4096])
    wgemm<false, false><<<dim3(CC / 128, CC / 128, BB), 256, WG_SMEM>>>(
        qkv + (long)CC * LL, qkv + (long)2 * CC * LL, ctx, nullptr,
        CC, LL, sQKV, sQKV, sCtx, LL, LL, CC);

    // 4) M[b] = w_out @ ctx[b]^T      (NT: B = ctx stored [N=512, K=512])
    wgemm<false, false><<<dim3(CC / 128, CC / 128, BB), 256, WG_SMEM>>>(
        w_out, ctx, Mm, nullptr, CC, CC, 0, sCtx, sCtx, CC, CC, CC);

    // 5) y[b] = M[b] @ q[b] + b_out   (NN: B = q stored [K=512, N=4096])
    wgemm<true, true><<<dim3(LL / 128, CC / 128, BB), 256, WG_SMEM>>>(
        Mm, qkv, y, b_out, LL, CC, sCtx, sQKV, sX, CC, LL, LL);

    (void)out_size;
}

// round 4
// speedup vs baseline: 2.7539x; 1.2665x over previous
#include <cuda_runtime.h>
#include <cuda_bf16.h>
#include <cstdint>

// Problem shape (fixed)
#define BB 16
#define CC 512
#define LL 4096

typedef __nv_bfloat16 bf16;

// ---------------- Scratch (device globals; no allocation allowed) -----------
__device__ __align__(256) float g_kf[(size_t)BB * CC * LL];     // k pre-softmax fp32
__device__ __align__(256) bf16 g_xh[(size_t)BB * CC * LL];
__device__ __align__(256) bf16 g_xl[(size_t)BB * CC * LL];
__device__ __align__(256) bf16 g_qh[(size_t)BB * CC * LL];
__device__ __align__(256) bf16 g_ql[(size_t)BB * CC * LL];
__device__ __align__(256) bf16 g_vh[(size_t)BB * CC * LL];
__device__ __align__(256) bf16 g_vl[(size_t)BB * CC * LL];
__device__ __align__(256) bf16 g_kh[(size_t)BB * CC * LL];
__device__ __align__(256) bf16 g_kl[(size_t)BB * CC * LL];
__device__ __align__(256) bf16 g_ch[(size_t)BB * CC * CC];
__device__ __align__(256) bf16 g_cl[(size_t)BB * CC * CC];
__device__ __align__(256) bf16 g_mh[(size_t)BB * CC * CC];
__device__ __align__(256) bf16 g_ml[(size_t)BB * CC * CC];
__device__ __align__(256) bf16 g_wqh[3 * CC * CC];
__device__ __align__(256) bf16 g_wql[3 * CC * CC];
__device__ __align__(256) bf16 g_woh[CC * CC];
__device__ __align__(256) bf16 g_wol[CC * CC];

// ---------------- PTX helpers ----------------
__device__ __forceinline__ uint32_t smem_u32(const void* p) {
    uint32_t a;
    asm("{ .reg .u64 t; cvta.to.shared.u64 t, %1; cvt.u32.u64 %0, t; }" : "=r"(a) : "l"(p));
    return a;
}
#define LDSM4(r0, r1, r2, r3, addr) \
    asm volatile("ldmatrix.sync.aligned.m8n8.x4.shared.b16 {%0,%1,%2,%3}, [%4];" \
                 : "=r"(r0), "=r"(r1), "=r"(r2), "=r"(r3) : "r"(addr))
#define LDSM4T(r0, r1, r2, r3, addr) \
    asm volatile("ldmatrix.sync.aligned.m8n8.x4.trans.shared.b16 {%0,%1,%2,%3}, [%4];" \
                 : "=r"(r0), "=r"(r1), "=r"(r2), "=r"(r3) : "r"(addr))
#define MMA16816(c, a, b) \
    asm volatile("mma.sync.aligned.m16n8k16.row.col.f32.bf16.bf16.f32 " \
                 "{%0,%1,%2,%3}, {%4,%5,%6,%7}, {%8,%9}, {%0,%1,%2,%3};" \
                 : "+f"((c)[0]), "+f"((c)[1]), "+f"((c)[2]), "+f"((c)[3]) \
                 : "r"((a)[0]), "r"((a)[1]), "r"((a)[2]), "r"((a)[3]), \
                   "r"((b)[0]), "r"((b)[1]))
#define CP16(dst, src) \
    asm volatile("cp.async.cg.shared.global [%0], [%1], 16;" :: "r"(dst), "l"(src))
#define CP_COMMIT() asm volatile("cp.async.commit_group;" ::: "memory")
#define CP_WAIT(n)  asm volatile("cp.async.wait_group %0;" :: "n"(n) : "memory")

__device__ __forceinline__ void split2(float f0, float f1, uint32_t& hi, uint32_t& lo) {
    __nv_bfloat162 h = __floats2bfloat162_rn(f0, f1);
    float r0 = f0 - __bfloat162float(h.x);
    float r1 = f1 - __bfloat162float(h.y);
    __nv_bfloat162 l = __floats2bfloat162_rn(r0, r1);
    hi = *reinterpret_cast<uint32_t*>(&h);
    lo = *reinterpret_cast<uint32_t*>(&l);
}

// ============================================================================
// wgemm: C[m,n] = sum_k A[m,k] * B'[k,n], bf16 hi/lo split operands (x3 MMA).
//   B_IS_KN=true : B stored [K,N] row-major (NN)
//   B_IS_KN=false: B stored [N,K] row-major (NT)
//   EPI: 0 = fp32 out (+bias if ADD_BIAS), 1 = bf16 hi/lo out,
//        2 = GEMM1 special: third 0 -> (Ch,Cl)=q, third 1 -> Cf=k fp32,
//            third 2 -> (Ch2,Cl2)=v; thirds are 512-row slabs.
// Block 128x128, K-chunk 32, 4-stage cp.async ring, 256 thr (8 warps 2x4).
// ============================================================================
#define NSTAGE 4
#define STG_B  32768
#define WG_SMEM (NSTAGE * STG_B)   // 128 KB
#define P_AH 0
#define P_AL 8192
#define P_BH 16384
#define P_BL 24576

template <bool B_IS_KN, int EPI, bool ADD_BIAS>
__global__ __launch_bounds__(256, 1) void wgemm(
    const bf16* __restrict__ Ah, const bf16* __restrict__ Al,
    const bf16* __restrict__ Bh, const bf16* __restrict__ Bl,
    float* __restrict__ Cf, bf16* __restrict__ Ch, bf16* __restrict__ Cl,
    bf16* __restrict__ Ch2, bf16* __restrict__ Cl2,
    const float* __restrict__ bias,
    int K, long sA, long sB, long sC, int lda, int ldb, int ldc)
{
    extern __shared__ char smem[];
    const uint32_t sb = smem_u32(smem);

    const int tid  = threadIdx.x;
    const int lane = tid & 31;
    const int wid  = tid >> 5;
    const int wm   = wid >> 2;
    const int wn   = wid & 3;
    const int m0 = blockIdx.y * 128;
    const int n0 = blockIdx.x * 128;
    const long z = blockIdx.z;

    Ah += z * sA + (long)m0 * lda;
    Al += z * sA + (long)m0 * lda;
    const long boff = z * sB + (B_IS_KN ? (long)n0 : (long)n0 * ldb);
    Bh += boff;
    Bl += boff;
    if (EPI == 0 || EPI == 2) Cf += z * sC;
    if (EPI == 1 || EPI == 2) { Ch += z * sC; Cl += z * sC; }
    if (EPI == 2) { Ch2 += z * sC; Cl2 += z * sC; }

    const int ln15 = lane & 15;
    const int grp  = lane >> 4;
    const int sw64 = (ln15 >> 1) & 3;

    float acc[4][4][4];
    #pragma unroll
    for (int i = 0; i < 4; i++)
        #pragma unroll
        for (int j = 0; j < 4; j++)
            #pragma unroll
            for (int q = 0; q < 4; q++) acc[i][j][q] = 0.0f;

    // -------- cp.async stage fill: 32k-chunk of A(128xk) and B --------
    auto issue = [&](int chunk, int s) {
        const int k0 = chunk * 32;
        const uint32_t st = sb + s * STG_B;
        // A planes: [m][k] rows of 64B, swizzle c ^ ((row>>1)&3)
        #pragma unroll
        for (int i = 0; i < 2; i++) {
            const int seg = tid + i * 256;
            const int row = seg >> 2;
            const int c   = seg & 3;
            const uint32_t doff = row * 64 + (((c ^ ((row >> 1) & 3)) & 3) << 4);
            const long soff = (long)row * lda + k0 + c * 8;
            CP16(st + P_AH + doff, Ah + soff);
            CP16(st + P_AL + doff, Al + soff);
        }
        if (!B_IS_KN) {
            // B planes: [n][k] rows of 64B, same swizzle
            #pragma unroll
            for (int i = 0; i < 2; i++) {
                const int seg = tid + i * 256;
                const int row = seg >> 2;
                const int c   = seg & 3;
                const uint32_t doff = row * 64 + (((c ^ ((row >> 1) & 3)) & 3) << 4);
                const long soff = (long)row * ldb + k0 + c * 8;
                CP16(st + P_BH + doff, Bh + soff);
                CP16(st + P_BL + doff, Bl + soff);
            }
        } else {
            // B planes: [k][n] rows of 256B, swizzle c ^ (k&7)
            #pragma unroll
            for (int i = 0; i < 2; i++) {
                const int seg = tid + i * 256;
                const int k   = seg >> 4;
                const int c   = seg & 15;
                const uint32_t doff = k * 256 + (((c ^ (k & 7)) & 15) << 4);
                const long soff = (long)(k0 + k) * ldb + c * 8;
                CP16(st + P_BH + doff, Bh + soff);
                CP16(st + P_BL + doff, Bl + soff);
            }
        }
    };

    // -------- fragment loads --------
    int a_row_off[4];
    #pragma unroll
    for (int i = 0; i < 4; i++)
        a_row_off[i] = (wm * 64 + i * 16 + ln15) * 64;
    int b_row_off[2];
    #pragma unroll
    for (int jp = 0; jp < 2; jp++)
        b_row_off[jp] = (wn * 32 + jp * 16 + ln15) * 64;
    const int kn_k7 = ln15 & 7;

    auto lda_frags = [&](uint32_t plane, int ks, uint32_t af[4][4]) {
        const int c = ks * 2 + grp;
        #pragma unroll
        for (int i = 0; i < 4; i++) {
            uint32_t addr = plane + a_row_off[i] + (((c ^ sw64) & 3) << 4);
            LDSM4(af[i][0], af[i][1], af[i][2], af[i][3], addr);
        }
    };
    auto ldb_frags = [&](uint32_t plane, int ks, uint32_t bf[4][2]) {
        if (B_IS_KN) {
            const uint32_t krow = (uint32_t)(ks * 16 + ln15) << 8;
            #pragma unroll
            for (int jp = 0; jp < 2; jp++) {
                const int cn = wn * 4 + jp * 2 + grp;
                uint32_t addr = plane + krow + (((cn ^ kn_k7) & 15) << 4);
                uint32_t r0, r1, r2, r3;
                LDSM4T(r0, r1, r2, r3, addr);
                bf[jp * 2    ][0] = r0; bf[jp * 2    ][1] = r1;
                bf[jp * 2 + 1][0] = r2; bf[jp * 2 + 1][1] = r3;
            }
        } else {
            const int c = ks * 2 + grp;
            #pragma unroll
            for (int jp = 0; jp < 2; jp++) {
                uint32_t addr = plane + b_row_off[jp] + (((c ^ sw64) & 3) << 4);
                uint32_t r0, r1, r2, r3;
                LDSM4(r0, r1, r2, r3, addr);
                bf[jp * 2    ][0] = r0; bf[jp * 2    ][1] = r2;
                bf[jp * 2 + 1][0] = r1; bf[jp * 2 + 1][1] = r3;
            }
        }
    };
    auto mma_pass = [&](uint32_t af[4][4], uint32_t bf[4][2]) {
        #pragma unroll
        for (int i = 0; i < 4; i++)
            #pragma unroll
            for (int j = 0; j < 4; j++)
                MMA16816(acc[i][j], af[i], bf[j]);
    };
    auto compute_chunk = [&](int s) {
        const uint32_t base = sb + s * STG_B;
        #pragma unroll
        for (int ks = 0; ks < 2; ks++) {
            uint32_t ah[4][4], bh[4][2];
            lda_frags(base + P_AH, ks, ah);
            ldb_frags(base + P_BH, ks, bh);
            mma_pass(ah, bh);
            {
                uint32_t bl[4][2];
                ldb_frags(base + P_BL, ks, bl);
                mma_pass(ah, bl);
            }
            {
                uint32_t al[4][4];
                lda_frags(base + P_AL, ks, al);
                mma_pass(al, bh);
            }
        }
    };

    // -------- multistage main loop --------
    const int NC = K >> 5;
    #pragma unroll
    for (int s = 0; s < NSTAGE - 1; s++) {
        if (s < NC) { issue(s, s); }
        CP_COMMIT();
    }
    for (int c = 0; c < NC; c++) {
        CP_WAIT(NSTAGE - 2);
        __syncthreads();
        const int pf = c + NSTAGE - 1;
        if (pf < NC) { issue(pf, pf & (NSTAGE - 1)); }
        CP_COMMIT();
        compute_chunk(c & (NSTAGE - 1));
    }

    // -------- epilogue --------
    #pragma unroll
    for (int i = 0; i < 4; i++) {
        const int row = m0 + wm * 64 + i * 16 + (lane >> 2);
        #pragma unroll
        for (int j = 0; j < 4; j++) {
            const int col = n0 + wn * 32 + j * 8 + (lane & 3) * 2;
            if (EPI == 0) {
                float bv0 = 0.0f, bv1 = 0.0f;
                if (ADD_BIAS) { bv0 = bias[row]; bv1 = bias[row + 8]; }
                float2 v0 = make_float2(acc[i][j][0] + bv0, acc[i][j][1] + bv0);
                float2 v1 = make_float2(acc[i][j][2] + bv1, acc[i][j][3] + bv1);
                *reinterpret_cast<float2*>(&Cf[(long)row * ldc + col])       = v0;
                *reinterpret_cast<float2*>(&Cf[(long)(row + 8) * ldc + col]) = v1;
            } else if (EPI == 1) {
                uint32_t h0, l0, h1, l1;
                split2(acc[i][j][0], acc[i][j][1], h0, l0);
                split2(acc[i][j][2], acc[i][j][3], h1, l1);
                *reinterpret_cast<uint32_t*>(&Ch[(long)row * ldc + col])       = h0;
                *reinterpret_cast<uint32_t*>(&Cl[(long)row * ldc + col])       = l0;
                *reinterpret_cast<uint32_t*>(&Ch[(long)(row + 8) * ldc + col]) = h1;
                *reinterpret_cast<uint32_t*>(&Cl[(long)(row + 8) * ldc + col]) = l1;
            } else {
                const int third = blockIdx.y >> 2;
                const int lr = row & 511;
                if (third == 1) {
                    float2 v0 = make_float2(acc[i][j][0], acc[i][j][1]);
                    float2 v1 = make_float2(acc[i][j][2], acc[i][j][3]);
                    *reinterpret_cast<float2*>(&Cf[(long)lr * ldc + col])       = v0;
                    *reinterpret_cast<float2*>(&Cf[(long)(lr + 8) * ldc + col]) = v1;
                } else {
                    bf16* dh = (third == 0) ? Ch : Ch2;
                    bf16* dl = (third == 0) ? Cl : Cl2;
                    uint32_t h0, l0, h1, l1;
                    split2(acc[i][j][0], acc[i][j][1], h0, l0);
                    split2(acc[i][j][2], acc[i][j][3], h1, l1);
                    *reinterpret_cast<uint32_t*>(&dh[(long)lr * ldc + col])       = h0;
                    *reinterpret_cast<uint32_t*>(&dl[(long)lr * ldc + col])       = l0;
                    *reinterpret_cast<uint32_t*>(&dh[(long)(lr + 8) * ldc + col]) = h1;
                    *reinterpret_cast<uint32_t*>(&dl[(long)(lr + 8) * ldc + col]) = l1;
                }
            }
        }
    }
}

// ============================================================================
// split_arr: fp32 array -> bf16 hi/lo planes (4 elements / thread)
// ============================================================================
__global__ __launch_bounds__(256) void split_arr(
    const float* __restrict__ s, bf16* __restrict__ h, bf16* __restrict__ l, long n)
{
    long i = ((long)blockIdx.x * 256 + threadIdx.x) * 4;
    if (i >= n) return;
    float4 v = *reinterpret_cast<const float4*>(s + i);
    uint32_t h0, l0, h1, l1;
    split2(v.x, v.y, h0, l0);
    split2(v.z, v.w, h1, l1);
    *reinterpret_cast<uint2*>(h + i) = make_uint2(h0, h1);
    *reinterpret_cast<uint2*>(l + i) = make_uint2(l0, l1);
}

// ============================================================================
// softmax over L on kf fp32, writing bf16 hi/lo
// ============================================================================
__global__ __launch_bounds__(256) void softmax_split(
    const float* __restrict__ kf, bf16* __restrict__ kh, bf16* __restrict__ kl)
{
    const int r = blockIdx.x;
    const int b = blockIdx.y;
    const long off = ((long)b * CC + r) * LL;
    const float* p = kf + off;
    const int tid = threadIdx.x;
    __shared__ float red[8];

    float v[16];
    float mx = -1e30f;
    #pragma unroll
    for (int i = 0; i < 16; i++) { v[i] = p[tid + i * 256]; mx = fmaxf(mx, v[i]); }
    #pragma unroll
    for (int o = 16; o > 0; o >>= 1) mx = fmaxf(mx, __shfl_xor_sync(0xffffffffu, mx, o));
    if ((tid & 31) == 0) red[tid >> 5] = mx;
    __syncthreads();
    if (tid < 32) {
        float m2 = (tid < 8) ? red[tid] : -1e30f;
        #pragma unroll
        for (int o = 4; o > 0; o >>= 1) m2 = fmaxf(m2, __shfl_xor_sync(0xffffffffu, m2, o));
        if (tid == 0) red[0] = m2;
    }
    __syncthreads();
    mx = red[0];
    __syncthreads();

    float s = 0.0f;
    #pragma unroll
    for (int i = 0; i < 16; i++) { v[i] = __expf(v[i] - mx); s += v[i]; }
    #pragma unroll
    for (int o = 16; o > 0; o >>= 1) s += __shfl_xor_sync(0xffffffffu, s, o);
    if ((tid & 31) == 0) red[tid >> 5] = s;
    __syncthreads();
    if (tid < 32) {
        float s2 = (tid < 8) ? red[tid] : 0.0f;
        #pragma unroll
        for (int o = 4; o > 0; o >>= 1) s2 += __shfl_xor_sync(0xffffffffu, s2, o);
        if (tid == 0) red[0] = s2;
    }
    __syncthreads();
    const float inv = 1.0f / red[0];

    #pragma unroll
    for (int i = 0; i < 16; i++) {
        float f = v[i] * inv;
        bf16 h = __float2bfloat16_rn(f);
        bf16 l = __float2bfloat16_rn(f - __bfloat162float(h));
        kh[off + tid + i * 256] = h;
        kl[off + tid + i * 256] = l;
    }
}

// ============================================================================
extern "C" void kernel_launch(void* const* d_in, const int* in_sizes, int n_in,
                              void* d_out, int out_size)
{
    const float* x = nullptr; const float* w_qkv = nullptr;
    const float* w_out = nullptr; const float* b_out = nullptr;
    for (int i = 0; i < n_in; i++) {
        switch (in_sizes[i]) {
            case 33554432: x     = (const float*)d_in[i]; break;
            case 786432:   w_qkv = (const float*)d_in[i]; break;
            case 262144:   w_out = (const float*)d_in[i]; break;
            case 512:      b_out = (const float*)d_in[i]; break;
            default: break;
        }
    }
    float* y = (float*)d_out;

    float* kf;  cudaGetSymbolAddress((void**)&kf,  g_kf);
    bf16 *xh, *xl, *qh, *ql, *vh, *vl, *kh, *kl, *ch, *cl, *mh, *ml, *wqh, *wql, *woh, *wol;
    cudaGetSymbolAddress((void**)&xh, g_xh);   cudaGetSymbolAddress((void**)&xl, g_xl);
    cudaGetSymbolAddress((void**)&qh, g_qh);   cudaGetSymbolAddress((void**)&ql, g_ql);
    cudaGetSymbolAddress((void**)&vh, g_vh);   cudaGetSymbolAddress((void**)&vl, g_vl);
    cudaGetSymbolAddress((void**)&kh, g_kh);   cudaGetSymbolAddress((void**)&kl, g_kl);
    cudaGetSymbolAddress((void**)&ch, g_ch);   cudaGetSymbolAddress((void**)&cl, g_cl);
    cudaGetSymbolAddress((void**)&mh, g_mh);   cudaGetSymbolAddress((void**)&ml, g_ml);
    cudaGetSymbolAddress((void**)&wqh, g_wqh); cudaGetSymbolAddress((void**)&wql, g_wql);
    cudaGetSymbolAddress((void**)&woh, g_woh); cudaGetSymbolAddress((void**)&wol, g_wol);

    cudaFuncSetAttribute(wgemm<true,  2, false>, cudaFuncAttributeMaxDynamicSharedMemorySize, WG_SMEM);
    cudaFuncSetAttribute(wgemm<false, 1, false>, cudaFuncAttributeMaxDynamicSharedMemorySize, WG_SMEM);
    cudaFuncSetAttribute(wgemm<true,  0, true >, cudaFuncAttributeMaxDynamicSharedMemorySize, WG_SMEM);

    const long sBig = (long)CC * LL;     // per-batch stride for x/q/k/v/y
    const long sCtx = (long)CC * CC;

    // 0) pre-split inputs to bf16 hi/lo
    split_arr<<<(unsigned)((size_t)BB * CC * LL / 1024), 256>>>(x, xh, xl, (long)BB * CC * LL);
    split_arr<<<3 * CC * CC / 1024, 256>>>(w_qkv, wqh, wql, 3 * CC * CC);
    split_arr<<<CC * CC / 1024, 256>>>(w_out, woh, wol, CC * CC);

    // 1) qkv = w_qkv @ x  (NN), epilogue: q->hi/lo, k->fp32, v->hi/lo
    wgemm<true, 2, false><<<dim3(LL / 128, (3 * CC) / 128, BB), 256, WG_SMEM>>>(
        wqh, wql, xh, xl, kf, qh, ql, vh, vl, nullptr,
        CC, 0, sBig, sBig, CC, LL, LL);

    // 2) softmax over L on k, write hi/lo
    softmax_split<<<dim3(CC, BB), 256>>>(kf, kh, kl);

    // 3) ctx = k_sm @ v^T  (NT) -> hi/lo
    wgemm<false, 1, false><<<dim3(CC / 128, CC / 128, BB), 256, WG_SMEM>>>(
        kh, kl, vh, vl, nullptr, ch, cl, nullptr, nullptr, nullptr,
        LL, sBig, sBig, sCtx, LL, LL, CC);

    // 4) M = w_out @ ctx^T (NT) -> hi/lo
    wgemm<false, 1, false><<<dim3(CC / 128, CC / 128, BB), 256, WG_SMEM>>>(
        woh, wol, ch, cl, nullptr, mh, ml, nullptr, nullptr, nullptr,
        CC, 0, sCtx, sCtx, CC, CC, CC);

    // 5) y = M @ q + b_out (NN, fp32 + bias)
    wgemm<true, 0, true><<<dim3(LL / 128, CC / 128, BB), 256, WG_SMEM>>>(
        mh, ml, qh, ql, y, nullptr, nullptr, nullptr, nullptr, b_out,
        CC, sCtx, sBig, sBig, CC, LL, LL);

    (void)out_size;
}